// round 1
// baseline (speedup 1.0000x reference)
#include <cuda_runtime.h>
#include <cstdint>

#define NN 50000
#define HID 128
#define NREL 8
#define KDIM (NREL * HID + HID)   // 1152

// ---------------- scratch (static device globals; no allocation) ----------------
__device__ float g_agg[(size_t)NN * NREL * HID];   // 204.8 MB
__device__ float g_inv[(size_t)NN * NREL];         // counts, then 1/max(cnt,1)
__device__ float g_h[(size_t)NN * HID];            // layer-1 activations

// ---------------- kernels ----------------
__global__ void count_kernel(const int* __restrict__ dst, const int* __restrict__ rel,
                             int E, float* __restrict__ cnt) {
    int e = blockIdx.x * blockDim.x + threadIdx.x;
    if (e < E) atomicAdd(&cnt[dst[e] * NREL + rel[e]], 1.0f);
}

__global__ void inv_kernel(float* __restrict__ cnt, int n) {
    int i = blockIdx.x * blockDim.x + threadIdx.x;
    if (i < n) {
        float c = cnt[i];
        cnt[i] = 1.0f / fmaxf(c, 1.0f);
    }
}

// one warp per edge: gather 128 floats of x[src], vector-red into Agg[(dst,rel)]
__global__ void scatter_kernel(const int* __restrict__ src, const int* __restrict__ dst,
                               const int* __restrict__ rel, const float4* __restrict__ x4,
                               float4* __restrict__ agg4, int E) {
    int w = (blockIdx.x * blockDim.x + threadIdx.x) >> 5;
    int lane = threadIdx.x & 31;
    if (w >= E) return;
    int s = src[w], d = dst[w], r = rel[w];
    float4 v = x4[(size_t)s * 32 + lane];
    float4* p = agg4 + ((size_t)d * NREL + r) * 32 + lane;
    asm volatile("red.global.add.v4.f32 [%0], {%1, %2, %3, %4};"
                 :: "l"(p), "f"(v.x), "f"(v.y), "f"(v.z), "f"(v.w) : "memory");
}

// out[N,128] = [inv*Agg | X] @ [W ; root] + bias, optional relu
// A is logically [N, 1152]: k<1024 -> Agg[n,k]*inv[n, k>>7]; k>=1024 -> X[n, k-1024]
#define BM 128
#define BN 128
#define BK 16
__global__ __launch_bounds__(256, 2)
void gemm_kernel(const float* __restrict__ Agg, const float* __restrict__ inv,
                 const float* __restrict__ X, const float* __restrict__ W,
                 const float* __restrict__ root, const float* __restrict__ bias,
                 float* __restrict__ out, int N, int do_relu) {
    __shared__ float As[BK][BM + 4];   // +4 keeps 16B alignment of rows
    __shared__ float Bs[BK][BN];

    const int block_row = blockIdx.x * BM;
    const int tid = threadIdx.x;
    const int tx = tid & 15;        // 0..15 -> output cols tx*8..tx*8+7
    const int ty = tid >> 4;        // 0..15 -> output rows ty*8..ty*8+7

    float acc[8][8];
#pragma unroll
    for (int i = 0; i < 8; i++)
#pragma unroll
        for (int j = 0; j < 8; j++) acc[i][j] = 0.0f;

    for (int kb = 0; kb < KDIM; kb += BK) {
        // ---- load A tile: 128 rows x 16 k = 512 float4, 2 per thread ----
#pragma unroll
        for (int i = 0; i < 2; i++) {
            int idx = tid + i * 256;
            int row = idx >> 2;          // 0..127
            int k4  = (idx & 3) * 4;     // 0,4,8,12
            int grow = block_row + row;
            float4 v = make_float4(0.f, 0.f, 0.f, 0.f);
            float scale = 0.0f;
            if (grow < N) {
                if (kb < NREL * HID) {
                    v = *(const float4*)(Agg + (size_t)grow * (NREL * HID) + kb + k4);
                    scale = inv[(size_t)grow * NREL + (kb >> 7)];
                } else {
                    v = *(const float4*)(X + (size_t)grow * HID + (kb - NREL * HID) + k4);
                    scale = 1.0f;
                }
            }
            As[k4 + 0][row] = v.x * scale;
            As[k4 + 1][row] = v.y * scale;
            As[k4 + 2][row] = v.z * scale;
            As[k4 + 3][row] = v.w * scale;
        }
        // ---- load B tile: 16 k x 128 cols = 512 float4, 2 per thread ----
#pragma unroll
        for (int i = 0; i < 2; i++) {
            int idx = tid + i * 256;
            int krow = idx >> 5;          // 0..15
            int col  = (idx & 31) * 4;
            int gk = kb + krow;
            float4 v;
            if (gk < NREL * HID) v = *(const float4*)(W + (size_t)gk * HID + col);
            else                 v = *(const float4*)(root + (size_t)(gk - NREL * HID) * HID + col);
            *(float4*)&Bs[krow][col] = v;
        }
        __syncthreads();

        // ---- compute ----
#pragma unroll
        for (int kk = 0; kk < BK; kk++) {
            float a[8], b[8];
            float4 a0 = *(const float4*)&As[kk][ty * 8];
            float4 a1 = *(const float4*)&As[kk][ty * 8 + 4];
            float4 b0 = *(const float4*)&Bs[kk][tx * 8];
            float4 b1 = *(const float4*)&Bs[kk][tx * 8 + 4];
            a[0]=a0.x; a[1]=a0.y; a[2]=a0.z; a[3]=a0.w; a[4]=a1.x; a[5]=a1.y; a[6]=a1.z; a[7]=a1.w;
            b[0]=b0.x; b[1]=b0.y; b[2]=b0.z; b[3]=b0.w; b[4]=b1.x; b[5]=b1.y; b[6]=b1.z; b[7]=b1.w;
#pragma unroll
            for (int i = 0; i < 8; i++)
#pragma unroll
                for (int j = 0; j < 8; j++)
                    acc[i][j] = fmaf(a[i], b[j], acc[i][j]);
        }
        __syncthreads();
    }

    // ---- epilogue: + bias, optional relu ----
    float bcol[8];
#pragma unroll
    for (int j = 0; j < 8; j++) bcol[j] = bias[tx * 8 + j];

#pragma unroll
    for (int i = 0; i < 8; i++) {
        int grow = block_row + ty * 8 + i;
        if (grow < N) {
            float4 r0, r1;
            r0.x = acc[i][0] + bcol[0]; r0.y = acc[i][1] + bcol[1];
            r0.z = acc[i][2] + bcol[2]; r0.w = acc[i][3] + bcol[3];
            r1.x = acc[i][4] + bcol[4]; r1.y = acc[i][5] + bcol[5];
            r1.z = acc[i][6] + bcol[6]; r1.w = acc[i][7] + bcol[7];
            if (do_relu) {
                r0.x = fmaxf(r0.x, 0.f); r0.y = fmaxf(r0.y, 0.f);
                r0.z = fmaxf(r0.z, 0.f); r0.w = fmaxf(r0.w, 0.f);
                r1.x = fmaxf(r1.x, 0.f); r1.y = fmaxf(r1.y, 0.f);
                r1.z = fmaxf(r1.z, 0.f); r1.w = fmaxf(r1.w, 0.f);
            }
            *(float4*)(out + (size_t)grow * HID + tx * 8)     = r0;
            *(float4*)(out + (size_t)grow * HID + tx * 8 + 4) = r1;
        }
    }
}

// ---------------- launch ----------------
extern "C" void kernel_launch(void* const* d_in, const int* in_sizes, int n_in,
                              void* d_out, int out_size) {
    const int* edge_index = (const int*)d_in[0];   // [2, E]
    const int* edge_type  = (const int*)d_in[1];   // [E]
    const float* node_emb = (const float*)d_in[2]; // [N, 128]
    const float* W1    = (const float*)d_in[3];    // [8,128,128]
    const float* root1 = (const float*)d_in[4];    // [128,128]
    const float* b1    = (const float*)d_in[5];    // [128]
    const float* W2    = (const float*)d_in[6];
    const float* root2 = (const float*)d_in[7];
    const float* b2    = (const float*)d_in[8];
    float* out = (float*)d_out;

    const int E = in_sizes[0] / 2;
    const int* src = edge_index;
    const int* dst = edge_index + E;

    float *agg, *inv, *h;
    cudaGetSymbolAddress((void**)&agg, g_agg);
    cudaGetSymbolAddress((void**)&inv, g_inv);
    cudaGetSymbolAddress((void**)&h,   g_h);

    const int T = 256;
    const int gemm_blocks = (NN + BM - 1) / BM;

    // counts / inv (edge-dependent only; shared by both layers)
    cudaMemsetAsync(inv, 0, sizeof(float) * (size_t)NN * NREL, 0);
    count_kernel<<<(E + T - 1) / T, T>>>(dst, edge_type, E, inv);
    inv_kernel<<<(NN * NREL + T - 1) / T, T>>>(inv, NN * NREL);

    // ---- layer 1 ----
    cudaMemsetAsync(agg, 0, sizeof(float) * (size_t)NN * NREL * HID, 0);
    scatter_kernel<<<(E * 32 + T - 1) / T, T>>>(src, dst, edge_type,
                                                (const float4*)node_emb, (float4*)agg, E);
    gemm_kernel<<<gemm_blocks, T>>>(agg, inv, node_emb, W1, root1, b1, h, NN, 1);

    // ---- layer 2 ----
    cudaMemsetAsync(agg, 0, sizeof(float) * (size_t)NN * NREL * HID, 0);
    scatter_kernel<<<(E * 32 + T - 1) / T, T>>>(src, dst, edge_type,
                                                (const float4*)h, (float4*)agg, E);
    gemm_kernel<<<gemm_blocks, T>>>(agg, inv, h, W2, root2, b2, out, NN, 0);
}

// round 3
// speedup vs baseline: 2.0121x; 2.0121x over previous
#include <cuda_runtime.h>
#include <cuda_bf16.h>
#include <cstdint>

#define NN   50000
#define NPAD 50048              // 391 * 128
#define HID  128
#define NREL 8
#define KD   1152               // 8*128 + 128
#define BK   64
#define NCHUNK (KD / BK)        // 18

// ---------------- scratch (static device globals; no allocation) ----------------
__device__ float g_agg[(size_t)NPAD * NREL * HID];   // ~205 MB
__device__ float g_inv[(size_t)NPAD * NREL];
__device__ float g_h[(size_t)NPAD * HID];
__device__ __nv_bfloat16 g_bhi[HID * KD];            // B^T hi  [128][1152]
__device__ __nv_bfloat16 g_blo[HID * KD];            // B^T lo

// ---------------- warp MMA helpers (baseline PTX ISA; no sm_103a suffix needed) ----
__device__ __forceinline__ void ldmx4(uint32_t* r, uint32_t addr) {
    asm volatile("ldmatrix.sync.aligned.m8n8.x4.shared.b16 {%0,%1,%2,%3}, [%4];"
                 : "=r"(r[0]), "=r"(r[1]), "=r"(r[2]), "=r"(r[3]) : "r"(addr));
}
__device__ __forceinline__ void mma16816(float* c, const uint32_t* a, const uint32_t* b) {
    asm volatile("mma.sync.aligned.m16n8k16.row.col.f32.bf16.bf16.f32 "
                 "{%0,%1,%2,%3}, {%4,%5,%6,%7}, {%8,%9}, {%0,%1,%2,%3};"
                 : "+f"(c[0]), "+f"(c[1]), "+f"(c[2]), "+f"(c[3])
                 : "r"(a[0]), "r"(a[1]), "r"(a[2]), "r"(a[3]), "r"(b[0]), "r"(b[1]));
}
__device__ __forceinline__ uint32_t smem_u32(const void* p) {
    uint32_t a;
    asm("{ .reg .u64 t; cvta.to.shared.u64 t, %1; cvt.u32.u64 %0, t; }" : "=r"(a) : "l"(p));
    return a;
}

// ---------------- small kernels ----------------
__global__ void count_kernel(const int* __restrict__ dst, const int* __restrict__ rel,
                             int E, float* __restrict__ cnt) {
    int e = blockIdx.x * blockDim.x + threadIdx.x;
    if (e < E) atomicAdd(&cnt[dst[e] * NREL + rel[e]], 1.0f);
}

__global__ void inv_kernel(float* __restrict__ cnt, int n) {
    int i = blockIdx.x * blockDim.x + threadIdx.x;
    if (i < n) cnt[i] = 1.0f / fmaxf(cnt[i], 1.0f);
}

__global__ void scatter_kernel(const int* __restrict__ src, const int* __restrict__ dst,
                               const int* __restrict__ rel, const float4* __restrict__ x4,
                               float4* __restrict__ agg4, int E) {
    int w = (blockIdx.x * blockDim.x + threadIdx.x) >> 5;
    int lane = threadIdx.x & 31;
    if (w >= E) return;
    int s = src[w], d = dst[w], r = rel[w];
    float4 v = x4[(size_t)s * 32 + lane];
    float4* p = agg4 + ((size_t)d * NREL + r) * 32 + lane;
    asm volatile("red.global.add.v4.f32 [%0], {%1, %2, %3, %4};"
                 :: "l"(p), "f"(v.x), "f"(v.y), "f"(v.z), "f"(v.w) : "memory");
}

// B^T split: bhi/blo[f][k] = split( k<1024 ? W[k*128+f] : root[(k-1024)*128+f] )
__global__ void bconv_kernel(const float* __restrict__ W, const float* __restrict__ root,
                             __nv_bfloat16* __restrict__ bhi, __nv_bfloat16* __restrict__ blo) {
    int i = blockIdx.x * blockDim.x + threadIdx.x;
    if (i >= HID * KD) return;
    int k = i % KD;
    int f = i / KD;
    float v = (k < NREL * HID) ? W[(size_t)k * HID + f]
                               : root[(size_t)(k - NREL * HID) * HID + f];
    __nv_bfloat16 h = __float2bfloat16(v);
    bhi[i] = h;
    blo[i] = __float2bfloat16(v - __bfloat162float(h));
}

// ---------------- HMMA GEMM: out[128/CTA, 128] over K=1152, bf16x3 split ----------------
// smem tile offsets (each 16 KB): A_HI, A_LO, B_HI, B_LO; rows of 128B, swizzled:
// addr(row, kb) = row*128 + (kb ^ ((row&7)*16))
__global__ void __launch_bounds__(256, 2)
gemm_tc(const float* __restrict__ Agg, const float* __restrict__ inv,
        const float* __restrict__ X, const __nv_bfloat16* __restrict__ Bhi,
        const __nv_bfloat16* __restrict__ Blo, const float* __restrict__ bias,
        float* __restrict__ out, int xrows, int nmax, int do_relu) {
    extern __shared__ char smem[];
    const uint32_t sbase = smem_u32(smem);
    const uint32_t A_HI = 0, A_LO = 16384, B_HI = 32768, B_LO = 49152;

    const int tid = threadIdx.x, wid = tid >> 5, lid = tid & 31;
    const int block_row = blockIdx.x * 128;
    const int wm = wid >> 2;          // 0..1  -> M offset wm*64
    const int wn = wid & 3;           // 0..3  -> N offset wn*32

    // per-lane ldmatrix geometry
    const int arow = (lid & 15);                       // A: lanes 0-15 rows, 16-31 rows again, k+8
    const uint32_t akoff = (uint32_t)(lid >> 4) * 16;  // byte offset for k+8 half
    const uint32_t axor = (uint32_t)(arow & 7) * 16;
    const int brow = (lid & 7) + ((lid >> 4) * 8);     // B groups: [n0..7,k0][n0..7,k0+8][n0+8..,k0][n0+8..,k0+8]
    const uint32_t bkoff = (uint32_t)((lid >> 3) & 1) * 16;
    const uint32_t bxor = (uint32_t)(brow & 7) * 16;

    float acc[4][4][4];
#pragma unroll
    for (int i = 0; i < 4; i++)
#pragma unroll
        for (int j = 0; j < 4; j++)
#pragma unroll
            for (int v = 0; v < 4; v++) acc[i][j][v] = 0.0f;

    for (int c = 0; c < NCHUNK; c++) {
        // ---- stage A tile: 128 rows x 64 k fp32 -> bf16 hi/lo, inv-scaled ----
#pragma unroll
        for (int i = 0; i < 8; i++) {
            int idx = tid + i * 256;          // 0..2047
            int row = idx >> 4;               // 0..127
            int k4 = (idx & 15) * 4;          // 0..60
            int grow = block_row + row;
            float4 v = make_float4(0.f, 0.f, 0.f, 0.f);
            float scale = 1.0f;
            if (c < 16) {
                v = *(const float4*)(Agg + (size_t)grow * (NREL * HID) + c * BK + k4);
                scale = inv[(size_t)grow * NREL + (c >> 1)];
            } else if (grow < xrows) {
                v = *(const float4*)(X + (size_t)grow * HID + (c - 16) * BK + k4);
            }
            float f0 = v.x * scale, f1 = v.y * scale, f2 = v.z * scale, f3 = v.w * scale;
            __nv_bfloat162 h01 = __floats2bfloat162_rn(f0, f1);
            __nv_bfloat162 h23 = __floats2bfloat162_rn(f2, f3);
            __nv_bfloat162 l01 = __floats2bfloat162_rn(f0 - __bfloat162float(h01.x),
                                                       f1 - __bfloat162float(h01.y));
            __nv_bfloat162 l23 = __floats2bfloat162_rn(f2 - __bfloat162float(h23.x),
                                                       f3 - __bfloat162float(h23.y));
            uint32_t kb = (uint32_t)k4 * 2;
            uint32_t sw = (uint32_t)row * 128 + (kb ^ ((uint32_t)(row & 7) * 16));
            *(uint2*)(smem + A_HI + sw) = *(const uint2*)&h01;   // h01,h23 packed
            ((uint2*)(smem + A_HI + sw))->y = *(const uint32_t*)&h23;
            uint2 hv, lv;
            hv.x = *(const uint32_t*)&h01; hv.y = *(const uint32_t*)&h23;
            lv.x = *(const uint32_t*)&l01; lv.y = *(const uint32_t*)&l23;
            *(uint2*)(smem + A_HI + sw) = hv;
            *(uint2*)(smem + A_LO + sw) = lv;
        }
        // ---- stage B tiles: 128 n x 64 k bf16 (hi and lo) ----
#pragma unroll
        for (int i = 0; i < 8; i++) {
            int idx = tid + i * 256;          // 0..2047
            int buf = idx >> 10;              // 0=hi, 1=lo
            int r = (idx >> 3) & 127;
            int k16 = idx & 7;
            const __nv_bfloat16* srcb = buf ? Blo : Bhi;
            uint4 v = *(const uint4*)(srcb + (size_t)r * KD + c * BK + k16 * 8);
            uint32_t kb = (uint32_t)k16 * 16;
            uint32_t sw = (uint32_t)r * 128 + (kb ^ ((uint32_t)(r & 7) * 16));
            *(uint4*)(smem + (buf ? B_LO : B_HI) + sw) = v;
        }
        __syncthreads();

        // ---- compute: 4 x K16 steps, 3 MMA terms each ----
#pragma unroll
        for (int kk = 0; kk < 4; kk++) {
            uint32_t af[4][4], bf[4][2];
            uint32_t ak = (uint32_t)kk * 32 + akoff;
            uint32_t bk = (uint32_t)kk * 32 + bkoff;

            // A_hi frags (4 m-tiles)
#pragma unroll
            for (int mt = 0; mt < 4; mt++) {
                uint32_t off = (uint32_t)(wm * 64 + mt * 16 + arow) * 128 + (ak ^ axor);
                ldmx4(af[mt], sbase + A_HI + off);
            }
            // B_lo frags (2 pair-loads cover 4 n-tiles)
#pragma unroll
            for (int p = 0; p < 2; p++) {
                uint32_t r4[4];
                uint32_t off = (uint32_t)(wn * 32 + p * 16 + brow) * 128 + (bk ^ bxor);
                ldmx4(r4, sbase + B_LO + off);
                bf[2 * p][0] = r4[0]; bf[2 * p][1] = r4[1];
                bf[2 * p + 1][0] = r4[2]; bf[2 * p + 1][1] = r4[3];
            }
#pragma unroll
            for (int mt = 0; mt < 4; mt++)
#pragma unroll
                for (int nt = 0; nt < 4; nt++) mma16816(acc[mt][nt], af[mt], bf[nt]);

            // B_hi frags
#pragma unroll
            for (int p = 0; p < 2; p++) {
                uint32_t r4[4];
                uint32_t off = (uint32_t)(wn * 32 + p * 16 + brow) * 128 + (bk ^ bxor);
                ldmx4(r4, sbase + B_HI + off);
                bf[2 * p][0] = r4[0]; bf[2 * p][1] = r4[1];
                bf[2 * p + 1][0] = r4[2]; bf[2 * p + 1][1] = r4[3];
            }
#pragma unroll
            for (int mt = 0; mt < 4; mt++)
#pragma unroll
                for (int nt = 0; nt < 4; nt++) mma16816(acc[mt][nt], af[mt], bf[nt]);

            // A_lo frags
#pragma unroll
            for (int mt = 0; mt < 4; mt++) {
                uint32_t off = (uint32_t)(wm * 64 + mt * 16 + arow) * 128 + (ak ^ axor);
                ldmx4(af[mt], sbase + A_LO + off);
            }
#pragma unroll
            for (int mt = 0; mt < 4; mt++)
#pragma unroll
                for (int nt = 0; nt < 4; nt++) mma16816(acc[mt][nt], af[mt], bf[nt]);
        }
        __syncthreads();
    }

    // ---- epilogue: bias (+relu) ----
#pragma unroll
    for (int mt = 0; mt < 4; mt++) {
        int r0 = block_row + wm * 64 + mt * 16 + (lid >> 2);
#pragma unroll
        for (int nt = 0; nt < 4; nt++) {
            int col = wn * 32 + nt * 8 + (lid & 3) * 2;
            float b0 = bias[col], b1 = bias[col + 1];
            float2 o0, o1;
            o0.x = acc[mt][nt][0] + b0; o0.y = acc[mt][nt][1] + b1;
            o1.x = acc[mt][nt][2] + b0; o1.y = acc[mt][nt][3] + b1;
            if (do_relu) {
                o0.x = fmaxf(o0.x, 0.f); o0.y = fmaxf(o0.y, 0.f);
                o1.x = fmaxf(o1.x, 0.f); o1.y = fmaxf(o1.y, 0.f);
            }
            if (r0 < nmax)     *(float2*)(out + (size_t)r0 * HID + col) = o0;
            if (r0 + 8 < nmax) *(float2*)(out + (size_t)(r0 + 8) * HID + col) = o1;
        }
    }
}

// ---------------- launch ----------------
extern "C" void kernel_launch(void* const* d_in, const int* in_sizes, int n_in,
                              void* d_out, int out_size) {
    const int* edge_index = (const int*)d_in[0];
    const int* edge_type  = (const int*)d_in[1];
    const float* node_emb = (const float*)d_in[2];
    const float* W1    = (const float*)d_in[3];
    const float* root1 = (const float*)d_in[4];
    const float* b1    = (const float*)d_in[5];
    const float* W2    = (const float*)d_in[6];
    const float* root2 = (const float*)d_in[7];
    const float* b2    = (const float*)d_in[8];
    float* out = (float*)d_out;

    const int E = in_sizes[0] / 2;
    const int* src = edge_index;
    const int* dst = edge_index + E;

    float *agg, *inv, *h;
    __nv_bfloat16 *bhi, *blo;
    cudaGetSymbolAddress((void**)&agg, g_agg);
    cudaGetSymbolAddress((void**)&inv, g_inv);
    cudaGetSymbolAddress((void**)&h,   g_h);
    cudaGetSymbolAddress((void**)&bhi, g_bhi);
    cudaGetSymbolAddress((void**)&blo, g_blo);

    const int T = 256;
    const int gemm_blocks = NPAD / 128;   // 391
    const int SMEM_BYTES = 65536;
    static int configured = -1;
    if (configured < 0) {
        cudaFuncSetAttribute(gemm_tc, cudaFuncAttributeMaxDynamicSharedMemorySize, SMEM_BYTES);
        configured = 1;
    }

    // counts / inv (edge-dependent only; shared by both layers)
    cudaMemsetAsync(inv, 0, sizeof(float) * (size_t)NPAD * NREL, 0);
    count_kernel<<<(E + T - 1) / T, T>>>(dst, edge_type, E, inv);
    inv_kernel<<<((int)(NPAD * NREL) + T - 1) / T, T>>>(inv, NPAD * NREL);

    // ---- layer 1 ----
    bconv_kernel<<<(HID * KD + T - 1) / T, T>>>(W1, root1, bhi, blo);
    cudaMemsetAsync(agg, 0, sizeof(float) * (size_t)NPAD * NREL * HID, 0);
    scatter_kernel<<<(E * 32 + T - 1) / T, T>>>(src, dst, edge_type,
                                                (const float4*)node_emb, (float4*)agg, E);
    gemm_tc<<<gemm_blocks, 256, SMEM_BYTES>>>(agg, inv, node_emb, bhi, blo, b1, h,
                                              NN, NPAD, 1);

    // ---- layer 2 ----
    bconv_kernel<<<(HID * KD + T - 1) / T, T>>>(W2, root2, bhi, blo);
    cudaMemsetAsync(agg, 0, sizeof(float) * (size_t)NPAD * NREL * HID, 0);
    scatter_kernel<<<(E * 32 + T - 1) / T, T>>>(src, dst, edge_type,
                                                (const float4*)h, (float4*)agg, E);
    gemm_tc<<<gemm_blocks, 256, SMEM_BYTES>>>(agg, inv, h, bhi, blo, b2, out,
                                              NPAD, NN, 0);
}

// round 4
// speedup vs baseline: 2.5673x; 1.2760x over previous
#include <cuda_runtime.h>
#include <cuda_bf16.h>
#include <cstdint>

#define NN   50000
#define NPAD 50048              // 391 * 128
#define HID  128
#define NREL 8
#define ND   1152               // output cols: 8*128 rel blocks + 128 root block
#define KC   64                 // k-chunk
#define NCH  2                  // 128 / 64

// ---------------- scratch (static device globals; no allocation) ----------------
__device__ float g_z[(size_t)NPAD * (NREL * HID)];   // 205 MB transformed features
__device__ float g_t[(size_t)NPAD * HID];            // 25.6 MB layer-1 pre-relu output
__device__ float g_inv[(size_t)NN * NREL];
__device__ __nv_bfloat16 g_xhi[(size_t)NPAD * HID];  // 12.8 MB
__device__ __nv_bfloat16 g_xlo[(size_t)NPAD * HID];
__device__ __nv_bfloat16 g_bhi[ND * HID];            // B^T [1152][128]
__device__ __nv_bfloat16 g_blo[ND * HID];

// ---------------- warp MMA helpers ----------------
__device__ __forceinline__ void ldmx4(uint32_t* r, uint32_t addr) {
    asm volatile("ldmatrix.sync.aligned.m8n8.x4.shared.b16 {%0,%1,%2,%3}, [%4];"
                 : "=r"(r[0]), "=r"(r[1]), "=r"(r[2]), "=r"(r[3]) : "r"(addr));
}
__device__ __forceinline__ void mma16816(float* c, const uint32_t* a, const uint32_t* b) {
    asm volatile("mma.sync.aligned.m16n8k16.row.col.f32.bf16.bf16.f32 "
                 "{%0,%1,%2,%3}, {%4,%5,%6,%7}, {%8,%9}, {%0,%1,%2,%3};"
                 : "+f"(c[0]), "+f"(c[1]), "+f"(c[2]), "+f"(c[3])
                 : "r"(a[0]), "r"(a[1]), "r"(a[2]), "r"(a[3]), "r"(b[0]), "r"(b[1]));
}
__device__ __forceinline__ uint32_t smem_u32(const void* p) {
    uint32_t a;
    asm("{ .reg .u64 t; cvta.to.shared.u64 t, %1; cvt.u32.u64 %0, t; }" : "=r"(a) : "l"(p));
    return a;
}

// ---------------- small kernels ----------------
__global__ void count_kernel(const int* __restrict__ dst, const int* __restrict__ rel,
                             int E, float* __restrict__ cnt) {
    int e = blockIdx.x * blockDim.x + threadIdx.x;
    if (e < E) atomicAdd(&cnt[dst[e] * NREL + rel[e]], 1.0f);
}

__global__ void inv_kernel(float* __restrict__ cnt, int n) {
    int i = blockIdx.x * blockDim.x + threadIdx.x;
    if (i < n) cnt[i] = 1.0f / fmaxf(cnt[i], 1.0f);
}

// fp32 [srows,128] -> bf16 hi/lo [NPAD,128]; optional relu; zero pad rows
__global__ void xsplit_kernel(const float* __restrict__ src, int srows, int do_relu,
                              __nv_bfloat16* __restrict__ hi, __nv_bfloat16* __restrict__ lo) {
    int i = blockIdx.x * blockDim.x + threadIdx.x;   // one float4 per thread
    if (i >= NPAD * (HID / 4)) return;
    int row = i >> 5;
    float4 v = make_float4(0.f, 0.f, 0.f, 0.f);
    if (row < srows) v = ((const float4*)src)[i];
    if (do_relu) {
        v.x = fmaxf(v.x, 0.f); v.y = fmaxf(v.y, 0.f);
        v.z = fmaxf(v.z, 0.f); v.w = fmaxf(v.w, 0.f);
    }
    __nv_bfloat162 h01 = __floats2bfloat162_rn(v.x, v.y);
    __nv_bfloat162 h23 = __floats2bfloat162_rn(v.z, v.w);
    __nv_bfloat162 l01 = __floats2bfloat162_rn(v.x - __bfloat162float(h01.x),
                                               v.y - __bfloat162float(h01.y));
    __nv_bfloat162 l23 = __floats2bfloat162_rn(v.z - __bfloat162float(h23.x),
                                               v.w - __bfloat162float(h23.y));
    uint2 hv, lv;
    hv.x = *(const uint32_t*)&h01; hv.y = *(const uint32_t*)&h23;
    lv.x = *(const uint32_t*)&l01; lv.y = *(const uint32_t*)&l23;
    ((uint2*)hi)[i] = hv;
    ((uint2*)lo)[i] = lv;
}

// Bt[nn,k]: nn<1024 -> W[nn>>7, k, nn&127]; else root[k, nn-1024]; bf16 hi/lo split
__global__ void bconv_kernel(const float* __restrict__ W, const float* __restrict__ root,
                             __nv_bfloat16* __restrict__ bhi, __nv_bfloat16* __restrict__ blo) {
    int i = blockIdx.x * blockDim.x + threadIdx.x;
    if (i >= ND * HID) return;
    int nn = i >> 7, k = i & 127;
    float v = (nn < NREL * HID) ? W[((size_t)(nn >> 7) * HID + k) * HID + (nn & 127)]
                                : root[(size_t)k * HID + (nn - NREL * HID)];
    __nv_bfloat16 h = __float2bfloat16(v);
    bhi[i] = h;
    blo[i] = __float2bfloat16(v - __bfloat162float(h));
}

// out[dst] += inv[dst,rel] * z[src, rel*128 ..]; one warp per edge, red.v4 into L2-resident out
__global__ void scatter_kernel(const int* __restrict__ src, const int* __restrict__ dst,
                               const int* __restrict__ rel, const float* __restrict__ inv,
                               const float4* __restrict__ z4, float4* __restrict__ out4, int E) {
    int w = (blockIdx.x * blockDim.x + threadIdx.x) >> 5;
    int lane = threadIdx.x & 31;
    if (w >= E) return;
    int s = src[w], d = dst[w], r = rel[w];
    float scale = inv[d * NREL + r];
    float4 v = z4[((size_t)s * (NREL * HID) + r * HID) / 4 + lane];
    v.x *= scale; v.y *= scale; v.z *= scale; v.w *= scale;
    float4* p = out4 + (size_t)d * 32 + lane;
    asm volatile("red.global.add.v4.f32 [%0], {%1, %2, %3, %4};"
                 :: "l"(p), "f"(v.x), "f"(v.y), "f"(v.z), "f"(v.w) : "memory");
}

// ---------------- HMMA GEMM: [NPAD,128] x [128,1152], bf16x3, pre-split operands ----
// grid (9, 391): x = N-tile (fast -> A tile L2 reuse), y = M-tile
// smem (64KB): A_HI, A_LO, B_HI, B_LO each 16KB; rows of 128B, swizzle kb^((row&7)*16)
__global__ void __launch_bounds__(256, 2)
gemm_tc(const __nv_bfloat16* __restrict__ Ahi, const __nv_bfloat16* __restrict__ Alo,
        const __nv_bfloat16* __restrict__ Bhi, const __nv_bfloat16* __restrict__ Blo,
        float* __restrict__ z, float* __restrict__ tout,
        const float* __restrict__ bias, int tout_rows) {
    extern __shared__ char smem[];
    const uint32_t sbase = smem_u32(smem);
    const uint32_t A_HI = 0, A_LO = 16384, B_HI = 32768, B_LO = 49152;

    const int tid = threadIdx.x, wid = tid >> 5, lid = tid & 31;
    const int nt = blockIdx.x;               // 0..8
    const int block_row = blockIdx.y * 128;
    const int bcol = nt * 128;               // Bt row offset
    const int wm = wid >> 2, wn = wid & 3;

    const int arow = (lid & 15);
    const uint32_t akoff = (uint32_t)(lid >> 4) * 16;
    const uint32_t axor = (uint32_t)(arow & 7) * 16;
    const int brow = (lid & 7) + ((lid >> 4) * 8);
    const uint32_t bkoff = (uint32_t)((lid >> 3) & 1) * 16;
    const uint32_t bxor = (uint32_t)(brow & 7) * 16;

    float acc[4][4][4];
#pragma unroll
    for (int i = 0; i < 4; i++)
#pragma unroll
        for (int j = 0; j < 4; j++)
#pragma unroll
            for (int v = 0; v < 4; v++) acc[i][j][v] = 0.0f;

    for (int c = 0; c < NCH; c++) {
        // ---- stage A hi/lo: 128 rows x 64 k bf16 (direct, pre-split) ----
#pragma unroll
        for (int i = 0; i < 8; i++) {
            int idx = tid + i * 256;            // 0..2047
            int buf = idx >> 10;                // 0=hi 1=lo
            int r = (idx >> 3) & 127;
            int k16 = idx & 7;
            const __nv_bfloat16* srca = buf ? Alo : Ahi;
            uint4 v = *(const uint4*)(srca + (size_t)(block_row + r) * HID + c * KC + k16 * 8);
            uint32_t kb = (uint32_t)k16 * 16;
            uint32_t sw = (uint32_t)r * 128 + (kb ^ ((uint32_t)(r & 7) * 16));
            *(uint4*)(smem + (buf ? A_LO : A_HI) + sw) = v;
        }
        // ---- stage B hi/lo: 128 n x 64 k bf16 ----
#pragma unroll
        for (int i = 0; i < 8; i++) {
            int idx = tid + i * 256;
            int buf = idx >> 10;
            int r = (idx >> 3) & 127;
            int k16 = idx & 7;
            const __nv_bfloat16* srcb = buf ? Blo : Bhi;
            uint4 v = *(const uint4*)(srcb + (size_t)(bcol + r) * HID + c * KC + k16 * 8);
            uint32_t kb = (uint32_t)k16 * 16;
            uint32_t sw = (uint32_t)r * 128 + (kb ^ ((uint32_t)(r & 7) * 16));
            *(uint4*)(smem + (buf ? B_LO : B_HI) + sw) = v;
        }
        __syncthreads();

#pragma unroll
        for (int kk = 0; kk < 4; kk++) {
            uint32_t af[4][4], bf[4][2];
            uint32_t ak = (uint32_t)kk * 32 + akoff;
            uint32_t bk = (uint32_t)kk * 32 + bkoff;

#pragma unroll
            for (int mt = 0; mt < 4; mt++) {
                uint32_t off = (uint32_t)(wm * 64 + mt * 16 + arow) * 128 + (ak ^ axor);
                ldmx4(af[mt], sbase + A_HI + off);
            }
#pragma unroll
            for (int p = 0; p < 2; p++) {
                uint32_t r4[4];
                uint32_t off = (uint32_t)(wn * 32 + p * 16 + brow) * 128 + (bk ^ bxor);
                ldmx4(r4, sbase + B_LO + off);
                bf[2 * p][0] = r4[0]; bf[2 * p][1] = r4[1];
                bf[2 * p + 1][0] = r4[2]; bf[2 * p + 1][1] = r4[3];
            }
#pragma unroll
            for (int mt = 0; mt < 4; mt++)
#pragma unroll
                for (int nt2 = 0; nt2 < 4; nt2++) mma16816(acc[mt][nt2], af[mt], bf[nt2]);

#pragma unroll
            for (int p = 0; p < 2; p++) {
                uint32_t r4[4];
                uint32_t off = (uint32_t)(wn * 32 + p * 16 + brow) * 128 + (bk ^ bxor);
                ldmx4(r4, sbase + B_HI + off);
                bf[2 * p][0] = r4[0]; bf[2 * p][1] = r4[1];
                bf[2 * p + 1][0] = r4[2]; bf[2 * p + 1][1] = r4[3];
            }
#pragma unroll
            for (int mt = 0; mt < 4; mt++)
#pragma unroll
                for (int nt2 = 0; nt2 < 4; nt2++) mma16816(acc[mt][nt2], af[mt], bf[nt2]);

#pragma unroll
            for (int mt = 0; mt < 4; mt++) {
                uint32_t off = (uint32_t)(wm * 64 + mt * 16 + arow) * 128 + (ak ^ axor);
                ldmx4(af[mt], sbase + A_LO + off);
            }
#pragma unroll
            for (int mt = 0; mt < 4; mt++)
#pragma unroll
                for (int nt2 = 0; nt2 < 4; nt2++) mma16816(acc[mt][nt2], af[mt], bf[nt2]);
        }
        __syncthreads();
    }

    // ---- epilogue ----
    if (nt < 8) {
        // z block: no bias, no guard (z sized NPAD)
#pragma unroll
        for (int mt = 0; mt < 4; mt++) {
            int r0 = block_row + wm * 64 + mt * 16 + (lid >> 2);
#pragma unroll
            for (int nt2 = 0; nt2 < 4; nt2++) {
                int col = nt * 128 + wn * 32 + nt2 * 8 + (lid & 3) * 2;
                float2 o0 = make_float2(acc[mt][nt2][0], acc[mt][nt2][1]);
                float2 o1 = make_float2(acc[mt][nt2][2], acc[mt][nt2][3]);
                *(float2*)(z + (size_t)r0 * (NREL * HID) + col) = o0;
                *(float2*)(z + (size_t)(r0 + 8) * (NREL * HID) + col) = o1;
            }
        }
    } else {
        // root block: + bias, row guard
#pragma unroll
        for (int mt = 0; mt < 4; mt++) {
            int r0 = block_row + wm * 64 + mt * 16 + (lid >> 2);
#pragma unroll
            for (int nt2 = 0; nt2 < 4; nt2++) {
                int col = wn * 32 + nt2 * 8 + (lid & 3) * 2;
                float b0 = bias[col], b1 = bias[col + 1];
                float2 o0 = make_float2(acc[mt][nt2][0] + b0, acc[mt][nt2][1] + b1);
                float2 o1 = make_float2(acc[mt][nt2][2] + b0, acc[mt][nt2][3] + b1);
                if (r0 < tout_rows)     *(float2*)(tout + (size_t)r0 * HID + col) = o0;
                if (r0 + 8 < tout_rows) *(float2*)(tout + (size_t)(r0 + 8) * HID + col) = o1;
            }
        }
    }
}

// ---------------- launch ----------------
extern "C" void kernel_launch(void* const* d_in, const int* in_sizes, int n_in,
                              void* d_out, int out_size) {
    const int* edge_index = (const int*)d_in[0];
    const int* edge_type  = (const int*)d_in[1];
    const float* node_emb = (const float*)d_in[2];
    const float* W1    = (const float*)d_in[3];
    const float* root1 = (const float*)d_in[4];
    const float* b1    = (const float*)d_in[5];
    const float* W2    = (const float*)d_in[6];
    const float* root2 = (const float*)d_in[7];
    const float* b2    = (const float*)d_in[8];
    float* out = (float*)d_out;

    const int E = in_sizes[0] / 2;
    const int* src = edge_index;
    const int* dst = edge_index + E;

    float *z, *t, *inv;
    __nv_bfloat16 *xhi, *xlo, *bhi, *blo;
    cudaGetSymbolAddress((void**)&z,   g_z);
    cudaGetSymbolAddress((void**)&t,   g_t);
    cudaGetSymbolAddress((void**)&inv, g_inv);
    cudaGetSymbolAddress((void**)&xhi, g_xhi);
    cudaGetSymbolAddress((void**)&xlo, g_xlo);
    cudaGetSymbolAddress((void**)&bhi, g_bhi);
    cudaGetSymbolAddress((void**)&blo, g_blo);

    const int T = 256;
    const dim3 gemm_grid(9, NPAD / 128);
    const int SMEM_BYTES = 65536;
    static int configured = -1;
    if (configured < 0) {
        cudaFuncSetAttribute(gemm_tc, cudaFuncAttributeMaxDynamicSharedMemorySize, SMEM_BYTES);
        configured = 1;
    }

    // counts / inv (edge-dependent only; shared by both layers)
    cudaMemsetAsync(inv, 0, sizeof(float) * (size_t)NN * NREL, 0);
    count_kernel<<<(E + T - 1) / T, T>>>(dst, edge_type, E, inv);
    inv_kernel<<<(NN * NREL + T - 1) / T, T>>>(inv, NN * NREL);

    // ---- layer 1 ----
    bconv_kernel<<<(ND * HID + T - 1) / T, T>>>(W1, root1, bhi, blo);
    xsplit_kernel<<<(NPAD * 32 + T - 1) / T, T>>>(node_emb, NN, 0, xhi, xlo);
    gemm_tc<<<gemm_grid, T, SMEM_BYTES>>>(xhi, xlo, bhi, blo, z, t, b1, NPAD);
    scatter_kernel<<<(E * 32 + T - 1) / T, T>>>(src, dst, edge_type, inv,
                                                (const float4*)z, (float4*)t, E);

    // ---- layer 2 ----
    bconv_kernel<<<(ND * HID + T - 1) / T, T>>>(W2, root2, bhi, blo);
    xsplit_kernel<<<(NPAD * 32 + T - 1) / T, T>>>(t, NN, 1, xhi, xlo);
    gemm_tc<<<gemm_grid, T, SMEM_BYTES>>>(xhi, xlo, bhi, blo, z, out, b2, NN);
    scatter_kernel<<<(E * 32 + T - 1) / T, T>>>(src, dst, edge_type, inv,
                                                (const float4*)z, (float4*)out, E);
}